// round 10
// baseline (speedup 1.0000x reference)
#include <cuda_runtime.h>

// Fixed problem shape
#define MAX_N   100352
#define OUTC    516      // 512 feature cols + 4 layer cols
#define NFEAT   512

// Scratch (allocation-free: __device__ globals)
__device__ float g_p[MAX_N];      // projected value to scatter (h @ W_neigh)
__device__ float g_s0[MAX_N];     // x @ W_self0 (layer-0 self term)
__device__ float g_h[MAX_N];      // current layer activations
__device__ float g_neigh[MAX_N];  // scatter destination

// ---------------------------------------------------------------------------
// Zero output + neighbor accumulator
// ---------------------------------------------------------------------------
__global__ void k_zero(float* __restrict__ out, int out_n, int n_nodes) {
    int i = blockIdx.x * blockDim.x + threadIdx.x;
    if (i < out_n)  out[i] = 0.0f;
    if (i < n_nodes) g_neigh[i] = 0.0f;
}

// ---------------------------------------------------------------------------
// Fused feature pass over x:
//   - g_p[i]  = dot(x[i], W_neigh0)
//   - g_s0[i] = dot(x[i], W_self0)
//   - out[g, 0:512] += x[i, :]   (per-graph column sums; graph_ids sorted,
//     so per-warp contiguous chunks flush only on graph-run boundaries)
// One warp owns a contiguous chunk of nodes. Each lane owns 16 fixed columns
// (4x float4 at col = j*128 + lane*4).
// ---------------------------------------------------------------------------
__global__ void k_feat(const float* __restrict__ x,
                       const int*   __restrict__ gid,
                       const float* __restrict__ Wn,
                       const float* __restrict__ Ws,
                       float* __restrict__ out,
                       int N, int total_warps)
{
    int wid  = (blockIdx.x * blockDim.x + threadIdx.x) >> 5;
    int lane = threadIdx.x & 31;
    int npw  = (N + total_warps - 1) / total_warps;
    int start = wid * npw;
    int end   = min(start + npw, N);
    if (start >= end) return;

    float4 wn[4], ws[4];
#pragma unroll
    for (int j = 0; j < 4; j++) {
        wn[j] = reinterpret_cast<const float4*>(Wn)[j * 32 + lane];
        ws[j] = reinterpret_cast<const float4*>(Ws)[j * 32 + lane];
    }

    float4 acc[4];
#pragma unroll
    for (int j = 0; j < 4; j++) acc[j] = make_float4(0.f, 0.f, 0.f, 0.f);

    int cur_g = gid[start];

#pragma unroll 2
    for (int i = start; i < end; i++) {
        float4 xi[4];
#pragma unroll
        for (int j = 0; j < 4; j++)
            xi[j] = reinterpret_cast<const float4*>(x)[(size_t)i * (NFEAT / 4) + j * 32 + lane];

        int g = gid[i];
        if (g != cur_g) {
            // flush accumulated graph sums
#pragma unroll
            for (int j = 0; j < 4; j++) {
                float* base = out + (size_t)cur_g * OUTC + j * 128 + lane * 4;
                atomicAdd(base + 0, acc[j].x);
                atomicAdd(base + 1, acc[j].y);
                atomicAdd(base + 2, acc[j].z);
                atomicAdd(base + 3, acc[j].w);
                acc[j] = make_float4(0.f, 0.f, 0.f, 0.f);
            }
            cur_g = g;
        }

        float dn = 0.f, ds = 0.f;
#pragma unroll
        for (int j = 0; j < 4; j++) {
            dn += xi[j].x * wn[j].x + xi[j].y * wn[j].y + xi[j].z * wn[j].z + xi[j].w * wn[j].w;
            ds += xi[j].x * ws[j].x + xi[j].y * ws[j].y + xi[j].z * ws[j].z + xi[j].w * ws[j].w;
            acc[j].x += xi[j].x; acc[j].y += xi[j].y; acc[j].z += xi[j].z; acc[j].w += xi[j].w;
        }
#pragma unroll
        for (int o = 16; o > 0; o >>= 1) {
            dn += __shfl_xor_sync(0xFFFFFFFFu, dn, o);
            ds += __shfl_xor_sync(0xFFFFFFFFu, ds, o);
        }
        if (lane == 0) { g_p[i] = dn; g_s0[i] = ds; }
    }

    // final flush
#pragma unroll
    for (int j = 0; j < 4; j++) {
        float* base = out + (size_t)cur_g * OUTC + j * 128 + lane * 4;
        atomicAdd(base + 0, acc[j].x);
        atomicAdd(base + 1, acc[j].y);
        atomicAdd(base + 2, acc[j].z);
        atomicAdd(base + 3, acc[j].w);
    }
}

// ---------------------------------------------------------------------------
// Edge scatter: g_neigh[dst] += g_p[src], 1 edge/thread.
// (Calibration: 16/th=185.2, 8/th=165.3, 4/th=163.9, 2/th=162.3, 1/th=160.5 —
//  shallow per-thread streams keep the L1tex wavefront queue uncongested.)
// ---------------------------------------------------------------------------
__global__ void k_scatter(const int* __restrict__ src,
                          const int* __restrict__ dst, int E)
{
    int e = blockIdx.x * blockDim.x + threadIdx.x;
    if (e < E) {
        int s = __ldg(src + e);
        int d = __ldg(dst + e);
        atomicAdd(&g_neigh[d], g_p[s]);
    }
}

// ---------------------------------------------------------------------------
// Pointwise layer finish:
//   h = relu(g_neigh + bias + self_term)
//   self_term = g_s0[i] (layer 0) or g_h[i]*w_self (layers 1..3)
//   g_p = h * w_next (if another conv follows); zero g_neigh for next scatter
//   out[g, 512+layer] += h  (warp-aggregated atomics; graph_ids sorted)
// ---------------------------------------------------------------------------
__global__ void k_point(const int* __restrict__ gid,
                        float* __restrict__ out,
                        const float* __restrict__ bias_p,
                        const float* __restrict__ wself_p,   // null for layer 0
                        const float* __restrict__ wnext_p,   // null for last layer
                        int layer, int N)
{
    int i  = blockIdx.x * blockDim.x + threadIdx.x;
    int ii = min(i, N - 1);
    int g  = gid[ii];
    float val = 0.f;

    if (i < N) {
        float self = (wself_p == nullptr) ? g_s0[i] : g_h[i] * (*wself_p);
        float h = g_neigh[i] + (*bias_p) + self;
        h = fmaxf(h, 0.0f);
        g_h[i] = h;
        if (wnext_p) g_p[i] = h * (*wnext_p);
        g_neigh[i] = 0.0f;
        val = h;
    }

    int  g0   = __shfl_sync(0xFFFFFFFFu, g, 0);
    bool same = __all_sync(0xFFFFFFFFu, g == g0);
    if (same) {
#pragma unroll
        for (int o = 16; o > 0; o >>= 1)
            val += __shfl_xor_sync(0xFFFFFFFFu, val, o);
        if ((threadIdx.x & 31) == 0)
            atomicAdd(&out[(size_t)g0 * OUTC + 512 + layer], val);
    } else if (i < N) {
        atomicAdd(&out[(size_t)g * OUTC + 512 + layer], val);
    }
}

// ---------------------------------------------------------------------------
extern "C" void kernel_launch(void* const* d_in, const int* in_sizes, int n_in,
                              void* d_out, int out_size)
{
    const float* x    = (const float*)d_in[0];
    const int*   esrc = (const int*)  d_in[1];
    const int*   edst = (const int*)  d_in[2];
    const int*   gid  = (const int*)  d_in[3];
    const float* Wn0  = (const float*)d_in[4];
    const float* Ws0  = (const float*)d_in[5];
    const float* b0   = (const float*)d_in[6];
    const float* Wnr  = (const float*)d_in[7];
    const float* Wsr  = (const float*)d_in[8];
    const float* br   = (const float*)d_in[9];
    float* out = (float*)d_out;

    int N = in_sizes[3];      // graph_ids count = n_nodes
    int E = in_sizes[1];      // edge count

    // 1. zero output + neighbor accumulator
    {
        int n = (out_size > N) ? out_size : N;
        k_zero<<<(n + 255) / 256, 256>>>(out, out_size, N);
    }

    // 2. fused feature pass — 592 blocks (32 warps/SM) for DRAM latency hiding
    //    (A/B vs. prior 296; flush atomics double to ~2.4M but REDG cost is
    //     ~+2-3 us vs. predicted -5-10 us latency-hiding gain)
    {
        const int BLOCKS = 592, THREADS = 256;
        k_feat<<<BLOCKS, THREADS>>>(x, gid, Wn0, Ws0, out, N, BLOCKS * (THREADS / 32));
    }

    // 3. four conv layers: scatter + pointwise
    int sc_blocks = (E + 255) / 256;
    int pw_blocks = (N + 255) / 256;
    for (int L = 0; L < 4; L++) {
        k_scatter<<<sc_blocks, 256>>>(esrc, edst, E);
        const float* bias  = (L == 0) ? b0 : (br + (L - 1));
        const float* wself = (L == 0) ? nullptr : (Wsr + (L - 1));
        const float* wnext = (L < 3) ? (Wnr + L) : nullptr;
        k_point<<<pw_blocks, 256>>>(gid, out, bias, wself, wnext, L, N);
    }
}

// round 11
// speedup vs baseline: 1.1178x; 1.1178x over previous
#include <cuda_runtime.h>

// Fixed problem shape
#define MAX_N   100352
#define OUTC    516      // 512 feature cols + 4 layer cols
#define NFEAT   512

// Scratch (allocation-free: __device__ globals)
__device__ float g_p[MAX_N];      // projected value to scatter (h @ W_neigh)
__device__ float g_s0[MAX_N];     // x @ W_self0 (layer-0 self term)
__device__ float g_h[MAX_N];      // current layer activations
__device__ float g_neigh[MAX_N];  // scatter destination

// ---------------------------------------------------------------------------
// Zero output + neighbor accumulator
// ---------------------------------------------------------------------------
__global__ void k_zero(float* __restrict__ out, int out_n, int n_nodes) {
    int i = blockIdx.x * blockDim.x + threadIdx.x;
    if (i < out_n)  out[i] = 0.0f;
    if (i < n_nodes) g_neigh[i] = 0.0f;
}

// ---------------------------------------------------------------------------
// Fused feature pass over x:
//   - g_p[i]  = dot(x[i], W_neigh0)
//   - g_s0[i] = dot(x[i], W_self0)
//   - out[g, 0:512] += x[i, :]   (per-graph column sums)
// One warp owns a contiguous chunk of nodes; each lane owns 16 fixed columns.
// Graph-run-boundary flushes (rare, ~64 chip-wide) go straight to gmem.
// FINAL per-warp accumulators are aggregated across the block in smem, then
// flushed with ONE set of 512 atomics per distinct graph per block
// (~6x fewer result atomics than per-warp flushing).
// ---------------------------------------------------------------------------
__global__ void k_feat(const float* __restrict__ x,
                       const int*   __restrict__ gid,
                       const float* __restrict__ Wn,
                       const float* __restrict__ Ws,
                       float* __restrict__ out,
                       int N, int total_warps)
{
    __shared__ float sacc[8][512];   // per-warp final accumulators
    __shared__ int   sgid[8];        // per-warp final graph (-1 = empty warp)

    int wib  = threadIdx.x >> 5;     // warp in block
    int lane = threadIdx.x & 31;
    int wid  = blockIdx.x * (blockDim.x >> 5) + wib;
    int npw  = (N + total_warps - 1) / total_warps;
    int start = wid * npw;
    int end   = min(start + npw, N);

    float4 acc[4];
#pragma unroll
    for (int j = 0; j < 4; j++) acc[j] = make_float4(0.f, 0.f, 0.f, 0.f);
    int cur_g = -1;

    if (start < end) {
        float4 wn[4], ws[4];
#pragma unroll
        for (int j = 0; j < 4; j++) {
            wn[j] = reinterpret_cast<const float4*>(Wn)[j * 32 + lane];
            ws[j] = reinterpret_cast<const float4*>(Ws)[j * 32 + lane];
        }

        cur_g = gid[start];

#pragma unroll 2
        for (int i = start; i < end; i++) {
            float4 xi[4];
#pragma unroll
            for (int j = 0; j < 4; j++)
                xi[j] = reinterpret_cast<const float4*>(x)[(size_t)i * (NFEAT / 4) + j * 32 + lane];

            int g = gid[i];
            if (g != cur_g) {
                // rare mid-chunk boundary: flush directly to gmem
#pragma unroll
                for (int j = 0; j < 4; j++) {
                    float* base = out + (size_t)cur_g * OUTC + j * 128 + lane * 4;
                    atomicAdd(base + 0, acc[j].x);
                    atomicAdd(base + 1, acc[j].y);
                    atomicAdd(base + 2, acc[j].z);
                    atomicAdd(base + 3, acc[j].w);
                    acc[j] = make_float4(0.f, 0.f, 0.f, 0.f);
                }
                cur_g = g;
            }

            float dn = 0.f, ds = 0.f;
#pragma unroll
            for (int j = 0; j < 4; j++) {
                dn += xi[j].x * wn[j].x + xi[j].y * wn[j].y + xi[j].z * wn[j].z + xi[j].w * wn[j].w;
                ds += xi[j].x * ws[j].x + xi[j].y * ws[j].y + xi[j].z * ws[j].z + xi[j].w * ws[j].w;
                acc[j].x += xi[j].x; acc[j].y += xi[j].y; acc[j].z += xi[j].z; acc[j].w += xi[j].w;
            }
#pragma unroll
            for (int o = 16; o > 0; o >>= 1) {
                dn += __shfl_xor_sync(0xFFFFFFFFu, dn, o);
                ds += __shfl_xor_sync(0xFFFFFFFFu, ds, o);
            }
            if (lane == 0) { g_p[i] = dn; g_s0[i] = ds; }
        }
    }

    // park final accumulator + graph id in smem
    if (lane == 0) sgid[wib] = cur_g;
#pragma unroll
    for (int j = 0; j < 4; j++)
        *reinterpret_cast<float4*>(&sacc[wib][j * 128 + lane * 4]) = acc[j];
    __syncthreads();

    // block-level reduction: one atomic set per distinct final graph
    int t = threadIdx.x;             // handles cols t and t+256
#pragma unroll
    for (int w = 0; w < 8; w++) {
        int dg = sgid[w];
        if (dg < 0) continue;
        bool first = true;
        for (int w2 = 0; w2 < w; w2++)
            if (sgid[w2] == dg) { first = false; break; }
        if (!first) continue;
        float s0 = 0.f, s1 = 0.f;
        for (int w2 = w; w2 < 8; w2++) {
            if (sgid[w2] == dg) {
                s0 += sacc[w2][t];
                s1 += sacc[w2][t + 256];
            }
        }
        atomicAdd(&out[(size_t)dg * OUTC + t],       s0);
        atomicAdd(&out[(size_t)dg * OUTC + t + 256], s1);
    }
}

// ---------------------------------------------------------------------------
// Edge scatter: g_neigh[dst] += g_p[src], 1 edge/thread.
// (Calibration: 16/th=185.2, 8/th=165.3, 4/th=163.9, 2/th=162.3, 1/th=160.5 —
//  shallow per-thread streams keep the L1tex wavefront queue uncongested.)
// ---------------------------------------------------------------------------
__global__ void k_scatter(const int* __restrict__ src,
                          const int* __restrict__ dst, int E)
{
    int e = blockIdx.x * blockDim.x + threadIdx.x;
    if (e < E) {
        int s = __ldg(src + e);
        int d = __ldg(dst + e);
        atomicAdd(&g_neigh[d], g_p[s]);
    }
}

// ---------------------------------------------------------------------------
// Pointwise layer finish:
//   h = relu(g_neigh + bias + self_term)
//   self_term = g_s0[i] (layer 0) or g_h[i]*w_self (layers 1..3)
//   g_p = h * w_next (if another conv follows); zero g_neigh for next scatter
//   out[g, 512+layer] += h  (warp-aggregated atomics; graph_ids sorted)
// ---------------------------------------------------------------------------
__global__ void k_point(const int* __restrict__ gid,
                        float* __restrict__ out,
                        const float* __restrict__ bias_p,
                        const float* __restrict__ wself_p,   // null for layer 0
                        const float* __restrict__ wnext_p,   // null for last layer
                        int layer, int N)
{
    int i  = blockIdx.x * blockDim.x + threadIdx.x;
    int ii = min(i, N - 1);
    int g  = gid[ii];
    float val = 0.f;

    if (i < N) {
        float self = (wself_p == nullptr) ? g_s0[i] : g_h[i] * (*wself_p);
        float h = g_neigh[i] + (*bias_p) + self;
        h = fmaxf(h, 0.0f);
        g_h[i] = h;
        if (wnext_p) g_p[i] = h * (*wnext_p);
        g_neigh[i] = 0.0f;
        val = h;
    }

    int  g0   = __shfl_sync(0xFFFFFFFFu, g, 0);
    bool same = __all_sync(0xFFFFFFFFu, g == g0);
    if (same) {
#pragma unroll
        for (int o = 16; o > 0; o >>= 1)
            val += __shfl_xor_sync(0xFFFFFFFFu, val, o);
        if ((threadIdx.x & 31) == 0)
            atomicAdd(&out[(size_t)g0 * OUTC + 512 + layer], val);
    } else if (i < N) {
        atomicAdd(&out[(size_t)g * OUTC + 512 + layer], val);
    }
}

// ---------------------------------------------------------------------------
extern "C" void kernel_launch(void* const* d_in, const int* in_sizes, int n_in,
                              void* d_out, int out_size)
{
    const float* x    = (const float*)d_in[0];
    const int*   esrc = (const int*)  d_in[1];
    const int*   edst = (const int*)  d_in[2];
    const int*   gid  = (const int*)  d_in[3];
    const float* Wn0  = (const float*)d_in[4];
    const float* Ws0  = (const float*)d_in[5];
    const float* b0   = (const float*)d_in[6];
    const float* Wnr  = (const float*)d_in[7];
    const float* Wsr  = (const float*)d_in[8];
    const float* br   = (const float*)d_in[9];
    float* out = (float*)d_out;

    int N = in_sizes[3];      // graph_ids count = n_nodes
    int E = in_sizes[1];      // edge count

    // 1. zero output + neighbor accumulator
    {
        int n = (out_size > N) ? out_size : N;
        k_zero<<<(n + 255) / 256, 256>>>(out, out_size, N);
    }

    // 2. fused feature pass — 296 blocks (proven), block-aggregated flushes
    {
        const int BLOCKS = 296, THREADS = 256;
        k_feat<<<BLOCKS, THREADS>>>(x, gid, Wn0, Ws0, out, N, BLOCKS * (THREADS / 32));
    }

    // 3. four conv layers: scatter + pointwise
    int sc_blocks = (E + 255) / 256;
    int pw_blocks = (N + 255) / 256;
    for (int L = 0; L < 4; L++) {
        k_scatter<<<sc_blocks, 256>>>(esrc, edst, E);
        const float* bias  = (L == 0) ? b0 : (br + (L - 1));
        const float* wself = (L == 0) ? nullptr : (Wsr + (L - 1));
        const float* wnext = (L < 3) ? (Wnr + L) : nullptr;
        k_point<<<pw_blocks, 256>>>(gid, out, bias, wself, wnext, L, N);
    }
}

// round 12
// speedup vs baseline: 1.1726x; 1.0490x over previous
#include <cuda_runtime.h>

// Fixed problem shape
#define MAX_N   100352
#define OUTC    516      // 512 feature cols + 4 layer cols
#define NFEAT   512

// Scratch (allocation-free: __device__ globals)
__device__ float g_p[MAX_N];      // projected value to scatter (h @ W_neigh)
__device__ float g_s0[MAX_N];     // x @ W_self0 (layer-0 self term)
__device__ float g_h[MAX_N];      // current layer activations
__device__ float g_neigh[MAX_N];  // scatter destination

// ---------------------------------------------------------------------------
// Zero output + neighbor accumulator
// ---------------------------------------------------------------------------
__global__ void k_zero(float* __restrict__ out, int out_n, int n_nodes) {
    int i = blockIdx.x * blockDim.x + threadIdx.x;
    if (i < out_n)  out[i] = 0.0f;
    if (i < n_nodes) g_neigh[i] = 0.0f;
}

// ---------------------------------------------------------------------------
// Fused feature pass over x:
//   - g_p[i]  = dot(x[i], W_neigh0)
//   - g_s0[i] = dot(x[i], W_self0)
//   - out[g, 0:512] += x[i, :]   (per-graph column sums)
// One warp owns a contiguous chunk of nodes; each lane owns 16 fixed columns.
// Graph-run-boundary flushes (rare, ~64 chip-wide) go straight to gmem.
// FINAL per-warp accumulators are aggregated across the block in smem, then
// flushed with ONE set of 512 atomics per distinct graph per block.
// __launch_bounds__(256,3): 3 CTAs/SM guaranteed -> 444 blocks = 1 wave.
// ---------------------------------------------------------------------------
__global__ void __launch_bounds__(256, 3)
k_feat(const float* __restrict__ x,
       const int*   __restrict__ gid,
       const float* __restrict__ Wn,
       const float* __restrict__ Ws,
       float* __restrict__ out,
       int N, int total_warps)
{
    __shared__ float sacc[8][512];   // per-warp final accumulators
    __shared__ int   sgid[8];        // per-warp final graph (-1 = empty warp)

    int wib  = threadIdx.x >> 5;     // warp in block
    int lane = threadIdx.x & 31;
    int wid  = blockIdx.x * (blockDim.x >> 5) + wib;
    int npw  = (N + total_warps - 1) / total_warps;
    int start = wid * npw;
    int end   = min(start + npw, N);

    float4 acc[4];
#pragma unroll
    for (int j = 0; j < 4; j++) acc[j] = make_float4(0.f, 0.f, 0.f, 0.f);
    int cur_g = -1;

    if (start < end) {
        float4 wn[4], ws[4];
#pragma unroll
        for (int j = 0; j < 4; j++) {
            wn[j] = reinterpret_cast<const float4*>(Wn)[j * 32 + lane];
            ws[j] = reinterpret_cast<const float4*>(Ws)[j * 32 + lane];
        }

        cur_g = gid[start];

#pragma unroll 2
        for (int i = start; i < end; i++) {
            float4 xi[4];
#pragma unroll
            for (int j = 0; j < 4; j++)
                xi[j] = reinterpret_cast<const float4*>(x)[(size_t)i * (NFEAT / 4) + j * 32 + lane];

            int g = gid[i];
            if (g != cur_g) {
                // rare mid-chunk boundary: flush directly to gmem
#pragma unroll
                for (int j = 0; j < 4; j++) {
                    float* base = out + (size_t)cur_g * OUTC + j * 128 + lane * 4;
                    atomicAdd(base + 0, acc[j].x);
                    atomicAdd(base + 1, acc[j].y);
                    atomicAdd(base + 2, acc[j].z);
                    atomicAdd(base + 3, acc[j].w);
                    acc[j] = make_float4(0.f, 0.f, 0.f, 0.f);
                }
                cur_g = g;
            }

            float dn = 0.f, ds = 0.f;
#pragma unroll
            for (int j = 0; j < 4; j++) {
                dn += xi[j].x * wn[j].x + xi[j].y * wn[j].y + xi[j].z * wn[j].z + xi[j].w * wn[j].w;
                ds += xi[j].x * ws[j].x + xi[j].y * ws[j].y + xi[j].z * ws[j].z + xi[j].w * ws[j].w;
                acc[j].x += xi[j].x; acc[j].y += xi[j].y; acc[j].z += xi[j].z; acc[j].w += xi[j].w;
            }
#pragma unroll
            for (int o = 16; o > 0; o >>= 1) {
                dn += __shfl_xor_sync(0xFFFFFFFFu, dn, o);
                ds += __shfl_xor_sync(0xFFFFFFFFu, ds, o);
            }
            if (lane == 0) { g_p[i] = dn; g_s0[i] = ds; }
        }
    }

    // park final accumulator + graph id in smem
    if (lane == 0) sgid[wib] = cur_g;
#pragma unroll
    for (int j = 0; j < 4; j++)
        *reinterpret_cast<float4*>(&sacc[wib][j * 128 + lane * 4]) = acc[j];
    __syncthreads();

    // block-level reduction: one atomic set per distinct final graph
    int t = threadIdx.x;             // handles cols t and t+256
#pragma unroll
    for (int w = 0; w < 8; w++) {
        int dg = sgid[w];
        if (dg < 0) continue;
        bool first = true;
        for (int w2 = 0; w2 < w; w2++)
            if (sgid[w2] == dg) { first = false; break; }
        if (!first) continue;
        float s0 = 0.f, s1 = 0.f;
        for (int w2 = w; w2 < 8; w2++) {
            if (sgid[w2] == dg) {
                s0 += sacc[w2][t];
                s1 += sacc[w2][t + 256];
            }
        }
        atomicAdd(&out[(size_t)dg * OUTC + t],       s0);
        atomicAdd(&out[(size_t)dg * OUTC + t + 256], s1);
    }
}

// ---------------------------------------------------------------------------
// Edge scatter: g_neigh[dst] += g_p[src], 1 edge/thread.
// (Calibration: 16/th=185.2, 8/th=165.3, 4/th=163.9, 2/th=162.3, 1/th=160.5 —
//  shallow per-thread streams keep the L1tex wavefront queue uncongested.)
// ---------------------------------------------------------------------------
__global__ void k_scatter(const int* __restrict__ src,
                          const int* __restrict__ dst, int E)
{
    int e = blockIdx.x * blockDim.x + threadIdx.x;
    if (e < E) {
        int s = __ldg(src + e);
        int d = __ldg(dst + e);
        atomicAdd(&g_neigh[d], g_p[s]);
    }
}

// ---------------------------------------------------------------------------
// Pointwise layer finish:
//   h = relu(g_neigh + bias + self_term)
//   self_term = g_s0[i] (layer 0) or g_h[i]*w_self (layers 1..3)
//   g_p = h * w_next (if another conv follows); zero g_neigh for next scatter
//   out[g, 512+layer] += h  (warp-aggregated atomics; graph_ids sorted)
// ---------------------------------------------------------------------------
__global__ void k_point(const int* __restrict__ gid,
                        float* __restrict__ out,
                        const float* __restrict__ bias_p,
                        const float* __restrict__ wself_p,   // null for layer 0
                        const float* __restrict__ wnext_p,   // null for last layer
                        int layer, int N)
{
    int i  = blockIdx.x * blockDim.x + threadIdx.x;
    int ii = min(i, N - 1);
    int g  = gid[ii];
    float val = 0.f;

    if (i < N) {
        float self = (wself_p == nullptr) ? g_s0[i] : g_h[i] * (*wself_p);
        float h = g_neigh[i] + (*bias_p) + self;
        h = fmaxf(h, 0.0f);
        g_h[i] = h;
        if (wnext_p) g_p[i] = h * (*wnext_p);
        g_neigh[i] = 0.0f;
        val = h;
    }

    int  g0   = __shfl_sync(0xFFFFFFFFu, g, 0);
    bool same = __all_sync(0xFFFFFFFFu, g == g0);
    if (same) {
#pragma unroll
        for (int o = 16; o > 0; o >>= 1)
            val += __shfl_xor_sync(0xFFFFFFFFu, val, o);
        if ((threadIdx.x & 31) == 0)
            atomicAdd(&out[(size_t)g0 * OUTC + 512 + layer], val);
    } else if (i < N) {
        atomicAdd(&out[(size_t)g * OUTC + 512 + layer], val);
    }
}

// ---------------------------------------------------------------------------
extern "C" void kernel_launch(void* const* d_in, const int* in_sizes, int n_in,
                              void* d_out, int out_size)
{
    const float* x    = (const float*)d_in[0];
    const int*   esrc = (const int*)  d_in[1];
    const int*   edst = (const int*)  d_in[2];
    const int*   gid  = (const int*)  d_in[3];
    const float* Wn0  = (const float*)d_in[4];
    const float* Ws0  = (const float*)d_in[5];
    const float* b0   = (const float*)d_in[6];
    const float* Wnr  = (const float*)d_in[7];
    const float* Wsr  = (const float*)d_in[8];
    const float* br   = (const float*)d_in[9];
    float* out = (float*)d_out;

    int N = in_sizes[3];      // graph_ids count = n_nodes
    int E = in_sizes[1];      // edge count

    // 1. zero output + neighbor accumulator
    {
        int n = (out_size > N) ? out_size : N;
        k_zero<<<(n + 255) / 256, 256>>>(out, out_size, N);
    }

    // 2. fused feature pass — 444 blocks = 3 CTAs/SM (launch_bounds-pinned),
    //    single wave, 24 warps/SM; block-aggregated flushes keep atomics ~1us
    {
        const int BLOCKS = 444, THREADS = 256;
        k_feat<<<BLOCKS, THREADS>>>(x, gid, Wn0, Ws0, out, N, BLOCKS * (THREADS / 32));
    }

    // 3. four conv layers: scatter + pointwise
    int sc_blocks = (E + 255) / 256;
    int pw_blocks = (N + 255) / 256;
    for (int L = 0; L < 4; L++) {
        k_scatter<<<sc_blocks, 256>>>(esrc, edst, E);
        const float* bias  = (L == 0) ? b0 : (br + (L - 1));
        const float* wself = (L == 0) ? nullptr : (Wsr + (L - 1));
        const float* wnext = (L < 3) ? (Wnr + L) : nullptr;
        k_point<<<pw_blocks, 256>>>(gid, out, bias, wself, wnext, L, N);
    }
}